// round 16
// baseline (speedup 1.0000x reference)
#include <cuda_runtime.h>
#include <cuda_bf16.h>
#include <cstdint>
#include <cfloat>

#define N_Q     2048
#define M_ROWS  100000
#define DIMS    128
#define KNN     5

#define NSLICES   9
#define TILE_R    128
#define NTILES    87
#define SLICE_LEN (NTILES * TILE_R)   // 11136; 9*11136 >= 100000
#define QT        64                   // queries per CTA
#define TPB       256                  // 8 warps

#define KEEP      4                    // kept per (query, 16-col subset, slice)
#define TPQ_TOT   32                   // 8 subsets * KEEP
#define RSEL      24                   // exact-refined candidates per query

// ---- device scratch ----
__device__ __nv_bfloat16 g_hiF2[N_Q * DIMS];     // bf16(-2*F)
__device__ __nv_bfloat16 g_hiB [M_ROWS * DIMS];  // bf16(B)
__device__ float g_y2[M_ROWS];
__device__ float g_cand_val[NSLICES][N_Q][TPQ_TOT];
__device__ int   g_cand_idx[NSLICES][N_Q][TPQ_TOT];

// ---- smem layout (bytes) ----
#define AB_STRIDE 272                  // 256B bf16 row + 16B pad: conflict-free LDSM
#define SM_A    0                      // 64*272  = 17408
#define SM_B0   17408                  // 128*272 = 34816
#define SM_B1   52224
#define SM_Y2   87040                  // float[2][128]
#define SMEM_TOTAL 88064

// ---------------------------------------------------------------------------
__device__ __forceinline__ uint32_t s2u(const void* p) {
    uint32_t a;
    asm("{ .reg .u64 t; cvta.to.shared.u64 t, %1; cvt.u32.u64 %0, t; }" : "=r"(a) : "l"(p));
    return a;
}
__device__ __forceinline__ void cp16(uint32_t dst, const void* src) {
    asm volatile("cp.async.cg.shared.global [%0], [%1], 16;" :: "r"(dst), "l"(src) : "memory");
}
__device__ __forceinline__ void ldsm_x4(uint32_t& r0, uint32_t& r1, uint32_t& r2, uint32_t& r3,
                                        uint32_t addr) {
    asm volatile("ldmatrix.sync.aligned.m8n8.x4.shared.b16 {%0,%1,%2,%3}, [%4];"
                 : "=r"(r0), "=r"(r1), "=r"(r2), "=r"(r3) : "r"(addr));
}
__device__ __forceinline__ void mma16816(float& d0, float& d1, float& d2, float& d3,
                                         uint32_t a0, uint32_t a1, uint32_t a2, uint32_t a3,
                                         uint32_t b0, uint32_t b1) {
    asm volatile("mma.sync.aligned.m16n8k16.row.col.f32.bf16.bf16.f32 "
                 "{%0,%1,%2,%3}, {%4,%5,%6,%7}, {%8,%9}, {%0,%1,%2,%3};"
                 : "+f"(d0), "+f"(d1), "+f"(d2), "+f"(d3)
                 : "r"(a0), "r"(a1), "r"(a2), "r"(a3), "r"(b0), "r"(b1));
}

// ---------------------------------------------------------------------------
// Convert: bf16(B) rows, bf16(-2*F) rows, y2 norms. One warp per row.
__global__ void convert_kernel(const float* __restrict__ F, const float* __restrict__ B) {
    int gw   = (blockIdx.x * blockDim.x + threadIdx.x) >> 5;
    int lane = threadIdx.x & 31;
    if (gw >= N_Q + M_ROWS) return;
    bool isF = gw < N_Q;
    int row  = isF ? gw : gw - N_Q;
    const float* src = (isF ? F : B) + (size_t)row * DIMS;
    float4 v = reinterpret_cast<const float4*>(src)[lane];
    if (!isF) {
        float s = v.x*v.x + v.y*v.y + v.z*v.z + v.w*v.w;
        #pragma unroll
        for (int o = 16; o; o >>= 1) s += __shfl_xor_sync(0xffffffffu, s, o);
        if (lane == 0) g_y2[row] = s;
    }
    float sc = isF ? -2.0f : 1.0f;
    __nv_bfloat162 p0{__float2bfloat16_rn(sc * v.x), __float2bfloat16_rn(sc * v.y)};
    __nv_bfloat162 p1{__float2bfloat16_rn(sc * v.z), __float2bfloat16_rn(sc * v.w)};
    __nv_bfloat162* hp = reinterpret_cast<__nv_bfloat162*>(isF ? g_hiF2 : g_hiB);
    hp[(size_t)row * 64 + 2 * lane]     = p0;
    hp[(size_t)row * 64 + 2 * lane + 1] = p1;
}

// ---------------------------------------------------------------------------
// Main: bf16 mma GEMM + in-register top-4 selection. 2 CTAs/SM.
// Odd-bx CTAs start their tile walk at NTILES/2 (wrap) to de-phase
// co-resident CTAs and interleave GEMM vs load/epilogue phases.
__global__ void __launch_bounds__(TPB, 2)
knn_mma_kernel() {
    extern __shared__ char smem[];
    const uint32_t sb = s2u(smem);
    float* y2s = reinterpret_cast<float*>(smem + SM_Y2);

    const int tid  = threadIdx.x;
    const int wid  = tid >> 5;
    const int lane = tid & 31;
    const int wm   = wid & 3;        // 4 m-chunks of 16 rows
    const int wn   = wid >> 2;       // 2 n-chunks of 64 cols
    const int qblock  = blockIdx.x * QT;
    const int slice   = blockIdx.y;
    const int row_beg = slice * SLICE_LEN;
    const int toff    = (blockIdx.x & 1) ? (NTILES / 2) : 0;   // de-phase

    // Stage A (64 queries): 1024 16B chunks, 4 per thread.
    #pragma unroll
    for (int i = 0; i < 4; i++) {
        int chunk = tid + TPB * i;
        int r = chunk >> 4, cc = chunk & 15;
        uint4 v = *reinterpret_cast<const uint4*>(
            reinterpret_cast<const char*>(g_hiF2) + ((size_t)(qblock + r) * 256 + cc * 16));
        *reinterpret_cast<uint4*>(smem + SM_A + r * AB_STRIDE + cc * 16) = v;
    }
    // Prefetch first tile (rotated index) into buffer 0.
    {
        int tb = row_beg + toff * TILE_R;
        #pragma unroll
        for (int i = 0; i < 8; i++) {
            int chunk = tid + TPB * i;
            int r = chunk >> 4, cc = chunk & 15;
            int rg = tb + r;
            int rc = rg < M_ROWS ? rg : M_ROWS - 1;
            cp16(sb + SM_B0 + r * AB_STRIDE + cc * 16,
                 reinterpret_cast<const char*>(g_hiB) + ((size_t)rc * 256 + cc * 16));
        }
        if (tid < 128) {
            int rg = tb + tid;
            y2s[tid] = (rg < M_ROWS) ? g_y2[rg] : FLT_MAX;
        }
        asm volatile("cp.async.commit_group;" ::: "memory");
    }
    __syncthreads();

    // Hoist A fragments (16-row m-tile -> 32 regs), loop-invariant.
    const int arow = lane & 15;
    const int acol = (lane >> 4) * 16;
    const int brow = (lane & 7) + (lane >> 4) * 8;
    const int bcol = ((lane >> 3) & 1) * 16;
    const uint32_t Abase = sb + SM_A + (wm * 16) * AB_STRIDE;
    uint32_t afr[8][4];
    #pragma unroll
    for (int ks = 0; ks < 8; ks++)
        ldsm_x4(afr[ks][0], afr[ks][1], afr[ks][2], afr[ks][3],
                Abase + arow * AB_STRIDE + ks * 32 + acol);

    // Selection state: two owned query-rows, top-KEEP (ascending) each.
    float tv0[KEEP], tv1[KEEP]; int ti0[KEEP], ti1[KEEP];
    #pragma unroll
    for (int k = 0; k < KEEP; k++) {
        tv0[k] = FLT_MAX; ti0[k] = -1;
        tv1[k] = FLT_MAX; ti1[k] = -1;
    }

    for (int it = 0; it < NTILES; it++) {
        int t = it + toff; if (t >= NTILES) t -= NTILES;       // rotated walk
        const int buf = it & 1;
        const uint32_t Bb = sb + (buf ? SM_B1 : SM_B0);

        __syncthreads();   // prev GEMM+select done; B[buf^1], y2s[buf^1] free

        if (it + 1 < NTILES) {
            int tn = it + 1 + toff; if (tn >= NTILES) tn -= NTILES;
            int tb = row_beg + tn * TILE_R;
            uint32_t Bn = sb + (buf ? SM_B0 : SM_B1);
            #pragma unroll
            for (int i = 0; i < 8; i++) {
                int chunk = tid + TPB * i;
                int r = chunk >> 4, cc = chunk & 15;
                int rg = tb + r;
                int rc = rg < M_ROWS ? rg : M_ROWS - 1;
                cp16(Bn + r * AB_STRIDE + cc * 16,
                     reinterpret_cast<const char*>(g_hiB) + ((size_t)rc * 256 + cc * 16));
            }
            if (tid < 128) {
                int rg = tb + tid;
                y2s[(buf ^ 1) * 128 + tid] = (rg < M_ROWS) ? g_y2[rg] : FLT_MAX;
            }
            asm volatile("cp.async.commit_group;" ::: "memory");
            asm volatile("cp.async.wait_group 1;" ::: "memory");
        } else {
            asm volatile("cp.async.wait_group 0;" ::: "memory");
        }
        __syncthreads();   // B[buf] visible

        // ---- GEMM: warp tile 16(q) x 64(r), K=128, A from registers
        float acc[8][4];
        #pragma unroll
        for (int nt = 0; nt < 8; nt++)
            #pragma unroll
            for (int e = 0; e < 4; e++) acc[nt][e] = 0.f;

        const uint32_t Bbase = Bb + (wn * 64) * AB_STRIDE;
        #pragma unroll
        for (int ks = 0; ks < 8; ks++) {
            uint32_t b[8][2];
            #pragma unroll
            for (int nt2 = 0; nt2 < 4; nt2++) {
                uint32_t r0, r1, r2, r3;
                ldsm_x4(r0, r1, r2, r3,
                        Bbase + (nt2 * 16 + brow) * AB_STRIDE + ks * 32 + bcol);
                b[nt2 * 2][0] = r0; b[nt2 * 2][1] = r1;
                b[nt2 * 2 + 1][0] = r2; b[nt2 * 2 + 1][1] = r3;
            }
            #pragma unroll
            for (int nt = 0; nt < 8; nt++)
                mma16816(acc[nt][0], acc[nt][1], acc[nt][2], acc[nt][3],
                         afr[ks][0], afr[ks][1], afr[ks][2], afr[ks][3],
                         b[nt][0], b[nt][1]);
        }

        // ---- in-register selection, min-gated
        const float* y2t = y2s + buf * 128;
        const int cbase = wn * 64 + 2 * (lane & 3);
        const int gidx  = row_beg + t * TILE_R + cbase;
        #pragma unroll
        for (int nt = 0; nt < 8; nt++) {
            int col = cbase + nt * 8;
            float2 y2p = *reinterpret_cast<const float2*>(y2t + col);
            float v00 = acc[nt][0] + y2p.x, v01 = acc[nt][1] + y2p.y;
            float v10 = acc[nt][2] + y2p.x, v11 = acc[nt][3] + y2p.y;
            int ib = gidx + nt * 8;

            if (fminf(v00, v01) < tv0[KEEP - 1]) {
                #pragma unroll
                for (int e = 0; e < 2; e++) {
                    float v = e ? v01 : v00;
                    if (v < tv0[KEEP - 1]) {
                        tv0[KEEP - 1] = v; ti0[KEEP - 1] = ib + e;
                        #pragma unroll
                        for (int k = KEEP - 1; k > 0; k--) {
                            if (tv0[k] < tv0[k - 1]) {
                                float tf = tv0[k - 1]; tv0[k - 1] = tv0[k]; tv0[k] = tf;
                                int   ti = ti0[k - 1]; ti0[k - 1] = ti0[k]; ti0[k] = ti;
                            }
                        }
                    }
                }
            }
            if (fminf(v10, v11) < tv1[KEEP - 1]) {
                #pragma unroll
                for (int e = 0; e < 2; e++) {
                    float v = e ? v11 : v10;
                    if (v < tv1[KEEP - 1]) {
                        tv1[KEEP - 1] = v; ti1[KEEP - 1] = ib + e;
                        #pragma unroll
                        for (int k = KEEP - 1; k > 0; k--) {
                            if (tv1[k] < tv1[k - 1]) {
                                float tf = tv1[k - 1]; tv1[k - 1] = tv1[k]; tv1[k] = tf;
                                int   ti = ti1[k - 1]; ti1[k - 1] = ti1[k]; ti1[k] = ti;
                            }
                        }
                    }
                }
            }
        }
    }

    // Write candidates: sub-list id = wn*4 + (lane&3), rows q0 and q0+8.
    const int q0  = qblock + wm * 16 + (lane >> 2);
    const int sub = wn * 4 + (lane & 3);
    #pragma unroll
    for (int k = 0; k < KEEP; k++) {
        g_cand_val[slice][q0][sub * KEEP + k]     = tv0[k];
        g_cand_idx[slice][q0][sub * KEEP + k]     = ti0[k];
        g_cand_val[slice][q0 + 8][sub * KEEP + k] = tv1[k];
        g_cand_idx[slice][q0 + 8][sub * KEEP + k] = ti1[k];
    }
}

// ---------------------------------------------------------------------------
// Refine: per query (one warp): approx-top-24 of 288 candidates -> exact fp32
// distances -> top-5 -> sqrt, normalize, mean.
__global__ void __launch_bounds__(256)
refine_kernel(const float* __restrict__ F, const float* __restrict__ B,
              const float* __restrict__ minv, const float* __restrict__ maxv,
              float* __restrict__ out) {
    __shared__ float sv[8][NSLICES * TPQ_TOT];
    __shared__ int   si[8][NSLICES * TPQ_TOT];
    __shared__ int   sel[8][RSEL];
    __shared__ float ex[8][RSEL];

    const int w    = threadIdx.x >> 5;
    const int lane = threadIdx.x & 31;
    const int q    = blockIdx.x * 8 + w;
    const int NC   = NSLICES * TPQ_TOT;   // 288

    for (int i = lane; i < NC; i += 32) {
        sv[w][i] = g_cand_val[i / TPQ_TOT][q][i % TPQ_TOT];
        si[w][i] = g_cand_idx[i / TPQ_TOT][q][i % TPQ_TOT];
    }
    __syncwarp();

    float4 xv = reinterpret_cast<const float4*>(F + (size_t)q * DIMS)[lane];
    float x2 = xv.x*xv.x + xv.y*xv.y + xv.z*xv.z + xv.w*xv.w;
    #pragma unroll
    for (int o = 16; o; o >>= 1) x2 += __shfl_xor_sync(0xffffffffu, x2, o);

    // Rank-select approx top-RSEL (strict order via (val, pos)).
    for (int i = lane; i < NC; i += 32) {
        float v = sv[w][i];
        int r = 0;
        for (int j = 0; j < NC; j++) {
            float u = sv[w][j];
            r += (u < v) || (u == v && j < i);
        }
        if (r < RSEL) sel[w][r] = si[w][i];
    }
    __syncwarp();

    for (int cc = 0; cc < RSEL; cc++) {
        int id = sel[w][cc];
        float d2 = FLT_MAX;
        if (id >= 0) {
            float4 yv = reinterpret_cast<const float4*>(B + (size_t)id * DIMS)[lane];
            float p = yv.x*yv.x + yv.y*yv.y + yv.z*yv.z + yv.w*yv.w
                    - 2.0f * (xv.x*yv.x + xv.y*yv.y + xv.z*yv.z + xv.w*yv.w);
            #pragma unroll
            for (int o = 16; o; o >>= 1) p += __shfl_xor_sync(0xffffffffu, p, o);
            d2 = x2 + p;
        }
        if (lane == 0) ex[w][cc] = d2;
    }
    __syncwarp();

    if (lane == 0) {
        float best[KNN];
        #pragma unroll
        for (int k = 0; k < KNN; k++) best[k] = FLT_MAX;
        #pragma unroll
        for (int cc = 0; cc < RSEL; cc++) {
            float v = ex[w][cc];
            if (v < best[KNN - 1]) {
                best[KNN - 1] = v;
                #pragma unroll
                for (int k = KNN - 1; k > 0; k--) {
                    if (best[k] < best[k - 1]) {
                        float tf = best[k - 1]; best[k - 1] = best[k]; best[k] = tf;
                    }
                }
            }
        }
        float mn = *minv, mx = *maxv;
        float inv = 1.f / (mx - mn);
        float sum = 0.f;
        #pragma unroll
        for (int k = 0; k < KNN; k++)
            sum += (sqrtf(fmaxf(best[k], 0.f)) - mn) * inv;
        out[q] = sum * (1.0f / KNN);
    }
}

// ---------------------------------------------------------------------------
extern "C" void kernel_launch(void* const* d_in, const int* in_sizes, int n_in,
                              void* d_out, int out_size) {
    const float* F    = (const float*)d_in[0];
    const float* B    = (const float*)d_in[1];
    const float* minv = (const float*)d_in[2];
    const float* maxv = (const float*)d_in[3];
    float* out = (float*)d_out;

    static bool attr_done = false;
    if (!attr_done) {
        cudaFuncSetAttribute(knn_mma_kernel,
                             cudaFuncAttributeMaxDynamicSharedMemorySize, SMEM_TOTAL);
        attr_done = true;
    }

    int conv_blocks = ((N_Q + M_ROWS) * 32 + 255) / 256;
    convert_kernel<<<conv_blocks, 256>>>(F, B);

    dim3 grid(N_Q / QT, NSLICES);
    knn_mma_kernel<<<grid, TPB, SMEM_TOTAL>>>();

    refine_kernel<<<N_Q / 8, 256>>>(F, B, minv, maxv, out);
}

// round 17
// speedup vs baseline: 1.1244x; 1.1244x over previous
#include <cuda_runtime.h>
#include <cuda_bf16.h>
#include <cstdint>
#include <cfloat>

#define N_Q     2048
#define M_ROWS  100000
#define DIMS    128
#define KNN     5

#define NSLICES   9
#define TILE_R    128
#define NTILES    87
#define SLICE_LEN (NTILES * TILE_R)   // 11136; 9*11136 >= 100000
#define QT        64                   // queries per CTA
#define TPB       256                  // 8 warps

#define KEEP      4                    // kept per (query, 16-col subset, slice)
#define TPQ_TOT   32                   // 8 subsets * KEEP (== warp size!)
#define RSEL      24                   // exact-refined candidates per query

// ---- device scratch ----
__device__ __nv_bfloat16 g_hiF2[N_Q * DIMS];     // bf16(-2*F)
__device__ __nv_bfloat16 g_hiB [M_ROWS * DIMS];  // bf16(B)
__device__ float g_y2[M_ROWS];
__device__ float g_cand_val[NSLICES][N_Q][TPQ_TOT];
__device__ int   g_cand_idx[NSLICES][N_Q][TPQ_TOT];

// ---- smem layout (bytes) ----
#define AB_STRIDE 272                  // 256B bf16 row + 16B pad: conflict-free LDSM
#define SM_A    0                      // 64*272  = 17408
#define SM_B0   17408                  // 128*272 = 34816
#define SM_B1   52224
#define SM_Y2   87040                  // float[2][128]
#define SMEM_TOTAL 88064

// ---------------------------------------------------------------------------
__device__ __forceinline__ uint32_t s2u(const void* p) {
    uint32_t a;
    asm("{ .reg .u64 t; cvta.to.shared.u64 t, %1; cvt.u32.u64 %0, t; }" : "=r"(a) : "l"(p));
    return a;
}
__device__ __forceinline__ void cp16(uint32_t dst, const void* src) {
    asm volatile("cp.async.cg.shared.global [%0], [%1], 16;" :: "r"(dst), "l"(src) : "memory");
}
__device__ __forceinline__ void ldsm_x4(uint32_t& r0, uint32_t& r1, uint32_t& r2, uint32_t& r3,
                                        uint32_t addr) {
    asm volatile("ldmatrix.sync.aligned.m8n8.x4.shared.b16 {%0,%1,%2,%3}, [%4];"
                 : "=r"(r0), "=r"(r1), "=r"(r2), "=r"(r3) : "r"(addr));
}
__device__ __forceinline__ void mma16816(float& d0, float& d1, float& d2, float& d3,
                                         uint32_t a0, uint32_t a1, uint32_t a2, uint32_t a3,
                                         uint32_t b0, uint32_t b1) {
    asm volatile("mma.sync.aligned.m16n8k16.row.col.f32.bf16.bf16.f32 "
                 "{%0,%1,%2,%3}, {%4,%5,%6,%7}, {%8,%9}, {%0,%1,%2,%3};"
                 : "+f"(d0), "+f"(d1), "+f"(d2), "+f"(d3)
                 : "r"(a0), "r"(a1), "r"(a2), "r"(a3), "r"(b0), "r"(b1));
}

// ---------------------------------------------------------------------------
// Convert: bf16(B) rows, bf16(-2*F) rows, y2 norms. 4 rows per warp.
__global__ void convert_kernel(const float* __restrict__ F, const float* __restrict__ B) {
    int gw   = (blockIdx.x * blockDim.x + threadIdx.x) >> 5;
    int lane = threadIdx.x & 31;
    #pragma unroll
    for (int rr = 0; rr < 4; rr++) {
        int idx = gw * 4 + rr;
        if (idx >= N_Q + M_ROWS) return;
        bool isF = idx < N_Q;
        int row  = isF ? idx : idx - N_Q;
        const float* src = (isF ? F : B) + (size_t)row * DIMS;
        float4 v = reinterpret_cast<const float4*>(src)[lane];
        if (!isF) {
            float s = v.x*v.x + v.y*v.y + v.z*v.z + v.w*v.w;
            #pragma unroll
            for (int o = 16; o; o >>= 1) s += __shfl_xor_sync(0xffffffffu, s, o);
            if (lane == 0) g_y2[row] = s;
        }
        float sc = isF ? -2.0f : 1.0f;
        __nv_bfloat162 p0{__float2bfloat16_rn(sc * v.x), __float2bfloat16_rn(sc * v.y)};
        __nv_bfloat162 p1{__float2bfloat16_rn(sc * v.z), __float2bfloat16_rn(sc * v.w)};
        __nv_bfloat162* hp = reinterpret_cast<__nv_bfloat162*>(isF ? g_hiF2 : g_hiB);
        hp[(size_t)row * 64 + 2 * lane]     = p0;
        hp[(size_t)row * 64 + 2 * lane + 1] = p1;
    }
}

// ---------------------------------------------------------------------------
// Main: bf16 mma GEMM + in-register top-4 selection. 2 CTAs/SM.
// (Round-7 champion configuration, verbatim.)
__global__ void __launch_bounds__(TPB, 2)
knn_mma_kernel() {
    extern __shared__ char smem[];
    const uint32_t sb = s2u(smem);
    float* y2s = reinterpret_cast<float*>(smem + SM_Y2);

    const int tid  = threadIdx.x;
    const int wid  = tid >> 5;
    const int lane = tid & 31;
    const int wm   = wid & 3;        // 4 m-chunks of 16 rows
    const int wn   = wid >> 2;       // 2 n-chunks of 64 cols
    const int qblock  = blockIdx.x * QT;
    const int slice   = blockIdx.y;
    const int row_beg = slice * SLICE_LEN;

    // Stage A (64 queries): 1024 16B chunks, 4 per thread.
    #pragma unroll
    for (int i = 0; i < 4; i++) {
        int chunk = tid + TPB * i;
        int r = chunk >> 4, cc = chunk & 15;
        uint4 v = *reinterpret_cast<const uint4*>(
            reinterpret_cast<const char*>(g_hiF2) + ((size_t)(qblock + r) * 256 + cc * 16));
        *reinterpret_cast<uint4*>(smem + SM_A + r * AB_STRIDE + cc * 16) = v;
    }
    // Prefetch B tile 0 into buffer 0.
    {
        #pragma unroll
        for (int i = 0; i < 8; i++) {
            int chunk = tid + TPB * i;
            int r = chunk >> 4, cc = chunk & 15;
            int rg = row_beg + r;
            int rc = rg < M_ROWS ? rg : M_ROWS - 1;
            cp16(sb + SM_B0 + r * AB_STRIDE + cc * 16,
                 reinterpret_cast<const char*>(g_hiB) + ((size_t)rc * 256 + cc * 16));
        }
        if (tid < 128) {
            int rg = row_beg + tid;
            y2s[tid] = (rg < M_ROWS) ? g_y2[rg] : FLT_MAX;
        }
        asm volatile("cp.async.commit_group;" ::: "memory");
    }
    __syncthreads();

    // Hoist A fragments (16-row m-tile -> 32 regs), loop-invariant.
    const int arow = lane & 15;
    const int acol = (lane >> 4) * 16;
    const int brow = (lane & 7) + (lane >> 4) * 8;
    const int bcol = ((lane >> 3) & 1) * 16;
    const uint32_t Abase = sb + SM_A + (wm * 16) * AB_STRIDE;
    uint32_t afr[8][4];
    #pragma unroll
    for (int ks = 0; ks < 8; ks++)
        ldsm_x4(afr[ks][0], afr[ks][1], afr[ks][2], afr[ks][3],
                Abase + arow * AB_STRIDE + ks * 32 + acol);

    // Selection state: two owned query-rows, top-KEEP (ascending) each.
    float tv0[KEEP], tv1[KEEP]; int ti0[KEEP], ti1[KEEP];
    #pragma unroll
    for (int k = 0; k < KEEP; k++) {
        tv0[k] = FLT_MAX; ti0[k] = -1;
        tv1[k] = FLT_MAX; ti1[k] = -1;
    }

    for (int t = 0; t < NTILES; t++) {
        const int buf = t & 1;
        const uint32_t Bb = sb + (buf ? SM_B1 : SM_B0);

        __syncthreads();   // prev GEMM+select done; B[buf^1], y2s[buf^1] free

        if (t + 1 < NTILES) {
            int tb = row_beg + (t + 1) * TILE_R;
            uint32_t Bn = sb + (buf ? SM_B0 : SM_B1);
            #pragma unroll
            for (int i = 0; i < 8; i++) {
                int chunk = tid + TPB * i;
                int r = chunk >> 4, cc = chunk & 15;
                int rg = tb + r;
                int rc = rg < M_ROWS ? rg : M_ROWS - 1;
                cp16(Bn + r * AB_STRIDE + cc * 16,
                     reinterpret_cast<const char*>(g_hiB) + ((size_t)rc * 256 + cc * 16));
            }
            if (tid < 128) {
                int rg = tb + tid;
                y2s[(buf ^ 1) * 128 + tid] = (rg < M_ROWS) ? g_y2[rg] : FLT_MAX;
            }
            asm volatile("cp.async.commit_group;" ::: "memory");
            asm volatile("cp.async.wait_group 1;" ::: "memory");
        } else {
            asm volatile("cp.async.wait_group 0;" ::: "memory");
        }
        __syncthreads();   // B[buf] visible

        // ---- GEMM: warp tile 16(q) x 64(r), K=128, A from registers
        float acc[8][4];
        #pragma unroll
        for (int nt = 0; nt < 8; nt++)
            #pragma unroll
            for (int e = 0; e < 4; e++) acc[nt][e] = 0.f;

        const uint32_t Bbase = Bb + (wn * 64) * AB_STRIDE;
        #pragma unroll
        for (int ks = 0; ks < 8; ks++) {
            uint32_t b[8][2];
            #pragma unroll
            for (int nt2 = 0; nt2 < 4; nt2++) {
                uint32_t r0, r1, r2, r3;
                ldsm_x4(r0, r1, r2, r3,
                        Bbase + (nt2 * 16 + brow) * AB_STRIDE + ks * 32 + bcol);
                b[nt2 * 2][0] = r0; b[nt2 * 2][1] = r1;
                b[nt2 * 2 + 1][0] = r2; b[nt2 * 2 + 1][1] = r3;
            }
            #pragma unroll
            for (int nt = 0; nt < 8; nt++)
                mma16816(acc[nt][0], acc[nt][1], acc[nt][2], acc[nt][3],
                         afr[ks][0], afr[ks][1], afr[ks][2], afr[ks][3],
                         b[nt][0], b[nt][1]);
        }

        // ---- in-register selection: d2 = acc + y2[col]; update top-KEEP lists
        const float* y2t = y2s + buf * 128;
        const int cbase = wn * 64 + 2 * (lane & 3);
        const int gidx  = row_beg + t * TILE_R + cbase;
        #pragma unroll
        for (int nt = 0; nt < 8; nt++) {
            int col = cbase + nt * 8;
            float2 y2p = *reinterpret_cast<const float2*>(y2t + col);
            float v00 = acc[nt][0] + y2p.x, v01 = acc[nt][1] + y2p.y;
            float v10 = acc[nt][2] + y2p.x, v11 = acc[nt][3] + y2p.y;
            int ib = gidx + nt * 8;

            #pragma unroll
            for (int e = 0; e < 2; e++) {
                float v = e ? v01 : v00;
                if (v < tv0[KEEP - 1]) {
                    tv0[KEEP - 1] = v; ti0[KEEP - 1] = ib + e;
                    #pragma unroll
                    for (int k = KEEP - 1; k > 0; k--) {
                        if (tv0[k] < tv0[k - 1]) {
                            float tf = tv0[k - 1]; tv0[k - 1] = tv0[k]; tv0[k] = tf;
                            int   ti = ti0[k - 1]; ti0[k - 1] = ti0[k]; ti0[k] = ti;
                        }
                    }
                }
            }
            #pragma unroll
            for (int e = 0; e < 2; e++) {
                float v = e ? v11 : v10;
                if (v < tv1[KEEP - 1]) {
                    tv1[KEEP - 1] = v; ti1[KEEP - 1] = ib + e;
                    #pragma unroll
                    for (int k = KEEP - 1; k > 0; k--) {
                        if (tv1[k] < tv1[k - 1]) {
                            float tf = tv1[k - 1]; tv1[k - 1] = tv1[k]; tv1[k] = tf;
                            int   ti = ti1[k - 1]; ti1[k - 1] = ti1[k]; ti1[k] = ti;
                        }
                    }
                }
            }
        }
    }

    // Write candidates: sub-list id = wn*4 + (lane&3), rows q0 and q0+8.
    const int q0  = qblock + wm * 16 + (lane >> 2);
    const int sub = wn * 4 + (lane & 3);
    #pragma unroll
    for (int k = 0; k < KEEP; k++) {
        g_cand_val[slice][q0][sub * KEEP + k]     = tv0[k];
        g_cand_idx[slice][q0][sub * KEEP + k]     = ti0[k];
        g_cand_val[slice][q0 + 8][sub * KEEP + k] = tv1[k];
        g_cand_idx[slice][q0 + 8][sub * KEEP + k] = ti1[k];
    }
}

// ---------------------------------------------------------------------------
// Refine: per query (one warp). Warp-argmin selects approx-top-24 of 288
// candidates (lane owns slice-k cell-lane slot: coalesced), then exact fp32
// distances -> top-5 -> sqrt, normalize, mean.
__global__ void __launch_bounds__(256)
refine_kernel(const float* __restrict__ F, const float* __restrict__ B,
              const float* __restrict__ minv, const float* __restrict__ maxv,
              float* __restrict__ out) {
    __shared__ int   sel[8][RSEL];
    __shared__ float ex[8][RSEL];

    const int w    = threadIdx.x >> 5;
    const int lane = threadIdx.x & 31;
    const int q    = blockIdx.x * 8 + w;

    // Lane-owned candidate slots: slot k = (slice k, cell lane). Coalesced.
    float rv[NSLICES]; int ri[NSLICES];
    #pragma unroll
    for (int k = 0; k < NSLICES; k++) {
        rv[k] = g_cand_val[k][q][lane];
        ri[k] = g_cand_idx[k][q][lane];
    }

    // Query vector + exact x2.
    float4 xv = reinterpret_cast<const float4*>(F + (size_t)q * DIMS)[lane];
    float x2 = xv.x*xv.x + xv.y*xv.y + xv.z*xv.z + xv.w*xv.w;
    #pragma unroll
    for (int o = 16; o; o >>= 1) x2 += __shfl_xor_sync(0xffffffffu, x2, o);

    // 24 rounds of warp argmin.
    for (int r = 0; r < RSEL; r++) {
        float m = rv[0]; int ms = 0;
        #pragma unroll
        for (int k = 1; k < NSLICES; k++)
            if (rv[k] < m) { m = rv[k]; ms = k; }
        float wm = m;
        #pragma unroll
        for (int o = 16; o; o >>= 1)
            wm = fminf(wm, __shfl_xor_sync(0xffffffffu, wm, o));
        unsigned msk = __ballot_sync(0xffffffffu, m == wm);
        int wl = __ffs(msk) - 1;
        int widx = __shfl_sync(0xffffffffu, ri[ms], wl);
        if (lane == wl) rv[ms] = FLT_MAX;
        if (lane == 0) sel[w][r] = widx;
    }
    __syncwarp();

    // Exact distances for the selected candidates.
    for (int cc = 0; cc < RSEL; cc++) {
        int id = sel[w][cc];
        float d2 = FLT_MAX;
        if (id >= 0) {
            float4 yv = reinterpret_cast<const float4*>(B + (size_t)id * DIMS)[lane];
            float p = yv.x*yv.x + yv.y*yv.y + yv.z*yv.z + yv.w*yv.w
                    - 2.0f * (xv.x*yv.x + xv.y*yv.y + xv.z*yv.z + xv.w*yv.w);
            #pragma unroll
            for (int o = 16; o; o >>= 1) p += __shfl_xor_sync(0xffffffffu, p, o);
            d2 = x2 + p;
        }
        if (lane == 0) ex[w][cc] = d2;
    }
    __syncwarp();

    if (lane == 0) {
        float best[KNN];
        #pragma unroll
        for (int k = 0; k < KNN; k++) best[k] = FLT_MAX;
        #pragma unroll
        for (int cc = 0; cc < RSEL; cc++) {
            float v = ex[w][cc];
            if (v < best[KNN - 1]) {
                best[KNN - 1] = v;
                #pragma unroll
                for (int k = KNN - 1; k > 0; k--) {
                    if (best[k] < best[k - 1]) {
                        float tf = best[k - 1]; best[k - 1] = best[k]; best[k] = tf;
                    }
                }
            }
        }
        float mn = *minv, mx = *maxv;
        float inv = 1.f / (mx - mn);
        float sum = 0.f;
        #pragma unroll
        for (int k = 0; k < KNN; k++)
            sum += (sqrtf(fmaxf(best[k], 0.f)) - mn) * inv;
        out[q] = sum * (1.0f / KNN);
    }
}

// ---------------------------------------------------------------------------
extern "C" void kernel_launch(void* const* d_in, const int* in_sizes, int n_in,
                              void* d_out, int out_size) {
    const float* F    = (const float*)d_in[0];
    const float* B    = (const float*)d_in[1];
    const float* minv = (const float*)d_in[2];
    const float* maxv = (const float*)d_in[3];
    float* out = (float*)d_out;

    static bool attr_done = false;
    if (!attr_done) {
        cudaFuncSetAttribute(knn_mma_kernel,
                             cudaFuncAttributeMaxDynamicSharedMemorySize, SMEM_TOTAL);
        attr_done = true;
    }

    // 4 rows per warp, 8 warps per block.
    int conv_blocks = (N_Q + M_ROWS + 31) / 32;
    convert_kernel<<<conv_blocks, 256>>>(F, B);

    dim3 grid(N_Q / QT, NSLICES);
    knn_mma_kernel<<<grid, TPB, SMEM_TOTAL>>>();

    refine_kernel<<<N_Q / 8, 256>>>(F, B, minv, maxv, out);
}